// round 3
// baseline (speedup 1.0000x reference)
#include <cuda_runtime.h>

#define NCTA   128
#define TPB    256
#define PP     1024
#define DD     32
#define RS     1032
#define MAXIT  30
#define EPSV   0.1f
#define LN2F   0.69314718055994530942f
#define ALPHA  14.4269504088896340736f   /* 1/(eps*ln2) */
#define THRESH 0.1f

typedef unsigned long long u64;

__device__ float    g_b2[4096];
__device__ float2   g_cp[NCTA * PP];
__device__ float    g_err[MAXIT];
__device__ double   g_cost[4];
__device__ unsigned g_count = 0;
__device__ volatile unsigned g_gen = 0;

struct Smem {
    float  K2[32 * RS];
    float  bb[PP];
    float  ystage[256 * DD];
    double redd[TPB];
    float  A2s[32];
    float  lmu2s[32];
    float  lnu2s[32];
    float  errAcc;
    float  Sx, Sy;
};

__device__ __forceinline__ float ex2f(float x){ float r; asm("ex2.approx.ftz.f32 %0, %1;" : "=f"(r) : "f"(x)); return r; }
__device__ __forceinline__ float lg2f(float x){ float r; asm("lg2.approx.f32 %0, %1;" : "=f"(r) : "f"(x)); return r; }
__device__ __forceinline__ u64 pk2(float lo, float hi){ u64 r; asm("mov.b64 %0, {%1, %2};" : "=l"(r) : "f"(lo), "f"(hi)); return r; }
__device__ __forceinline__ void upk2(u64 v, float& lo, float& hi){ asm("mov.b64 {%0, %1}, %2;" : "=f"(lo), "=f"(hi) : "l"(v)); }
__device__ __forceinline__ void fma2(u64& d, u64 a, u64 b){ asm("fma.rn.f32x2 %0, %1, %2, %0;" : "+l"(d) : "l"(a), "l"(b)); }
__device__ __forceinline__ u64 add2(u64 a, u64 b){ u64 r; asm("add.rn.f32x2 %0, %1, %2;" : "=l"(r) : "l"(a), "l"(b)); return r; }

__device__ __forceinline__ void gbar(unsigned target) {
    __syncthreads();
    if (threadIdx.x == 0) {
        __threadfence();
        if (atomicAdd(&g_count, 1u) == NCTA - 1u) {
            g_count = 0;
            __threadfence();
            g_gen = target;
        } else {
            while (g_gen != target) { }
            __threadfence();
        }
    }
    __syncthreads();
}

__global__ void __launch_bounds__(TPB, 1)
sinkhorn_kernel(const float* __restrict__ gx, const float* __restrict__ gy,
                const float* __restrict__ gxw, const float* __restrict__ gyw,
                float* __restrict__ gout)
{
    extern __shared__ __align__(16) char smraw[];
    Smem* S = reinterpret_cast<Smem*>(smraw);

    const int tid  = threadIdx.x;
    const int lane = tid & 31;
    const int warp = tid >> 5;
    const int bid  = blockIdx.x;
    const int nb   = bid >> 5;
    const int sub  = bid & 31;
    const int r0   = sub * 32;

    const unsigned g0 = g_gen;     // all CTAs read before any barrier release
    unsigned bk = 0;

    // zero per-launch global state (disjoint slices, before first barrier)
    if (tid < 32) g_b2[bid * 32 + tid] = 0.f;
    if (bid == 0) {
        if (tid < MAXIT) g_err[tid] = 0.f;
        if (tid < 4)     g_cost[tid] = 0.0;
    }

    // global weight sums (redundant per CTA, deterministic)
    {
        float px = 0.f, py = 0.f;
        for (int k = tid; k < 4096; k += TPB) { px += gxw[k]; py += gyw[k]; }
        S->redd[tid] = (double)px; __syncthreads();
        for (int s = TPB/2; s > 0; s >>= 1) { if (tid < s) S->redd[tid] += S->redd[tid+s]; __syncthreads(); }
        if (tid == 0) S->Sx = (float)S->redd[0];
        __syncthreads();
        S->redd[tid] = (double)py; __syncthreads();
        for (int s = TPB/2; s > 0; s >>= 1) { if (tid < s) S->redd[tid] += S->redd[tid+s]; __syncthreads(); }
        if (tid == 0) S->Sy = (float)S->redd[0];
        __syncthreads();
    }

    if (tid < 32) {
        S->lmu2s[tid] = lg2f(gxw[nb * PP + r0 + tid] / S->Sx + 1e-8f);
        S->lnu2s[tid] = lg2f(gyw[nb * PP + sub * 32 + tid] / S->Sy + 1e-8f);
        S->A2s[tid]   = 0.f;
    }

    // ---- build K2 = -C/(eps*ln2) in SMEM ----
    const float* ybase = gy + (size_t)nb * PP * DD;
    for (int c = tid; c < PP; c += TPB) {
        const float4* yc = (const float4*)(ybase + c * DD);
        float s = 0.f;
#pragma unroll
        for (int q = 0; q < 8; q++) { float4 v = yc[q]; s += v.x*v.x + v.y*v.y + v.z*v.z + v.w*v.w; }
        S->bb[c] = s * ALPHA;
    }
    float xv[32];
    {
        const float4* xr = (const float4*)(gx + (size_t)(nb * PP + r0 + lane) * DD);
#pragma unroll
        for (int q = 0; q < 8; q++) {
            float4 v = xr[q];
            xv[4*q] = v.x; xv[4*q+1] = v.y; xv[4*q+2] = v.z; xv[4*q+3] = v.w;
        }
    }
    float x2 = 0.f;
#pragma unroll
    for (int d = 0; d < 32; d++) x2 += xv[d] * xv[d];
    const float cx = ALPHA * x2;
    u64 xp[16];
#pragma unroll
    for (int q = 0; q < 16; q++) xp[q] = pk2(xv[2*q], xv[2*q+1]);
    __syncthreads();

    for (int chunk = 0; chunk < 4; chunk++) {
        const int j0 = chunk * 256;
        const float4* ysrc = (const float4*)(ybase + j0 * DD);
        float4* yst = (float4*)S->ystage;
#pragma unroll
        for (int q = 0; q < 8; q++) yst[tid + 256 * q] = ysrc[tid + 256 * q];
        __syncthreads();
#pragma unroll 4
        for (int m = 0; m < 32; m++) {
            const int jj = warp + 8 * m;
            const ulonglong2* yp = (const ulonglong2*)(S->ystage + jj * DD);
            u64 acc[4] = {0ull, 0ull, 0ull, 0ull};
#pragma unroll
            for (int q = 0; q < 8; q++) {
                ulonglong2 w = yp[q];
                fma2(acc[(2*q)   & 3], xp[2*q],     w.x);
                fma2(acc[(2*q+1) & 3], xp[2*q + 1], w.y);
            }
            u64 st = add2(add2(acc[0], acc[1]), add2(acc[2], acc[3]));
            float lo, hi; upk2(st, lo, hi);
            float dot = lo + hi;
            S->K2[lane * RS + j0 + jj] = fmaf(dot, 2.f * ALPHA, -(cx + S->bb[j0 + jj]));
        }
        __syncthreads();
    }

    gbar(g0 + (++bk));

    // ---- Sinkhorn iterations ----
    for (int iter = 0; iter < MAXIT; iter++) {
        if (iter > 0) {
            float ev = __ldcg(&g_err[iter - 1]);
            if (ev * (EPSV * LN2F * 0.25f) < THRESH) break;
        }

        // phase 1: row (u) update + column partials
        {
            const float4* gb4 = (const float4*)(g_b2 + nb * PP);
            ((float4*)S->bb)[tid] = __ldcg(gb4 + tid);
            if (tid == 0) S->errAcc = 0.f;
            __syncthreads();

#pragma unroll
            for (int k = 0; k < 4; k++) {
                const int r = warp * 4 + k;
                const float4* kr = (const float4*)(S->K2 + r * RS);
                const float4* b4 = (const float4*)S->bb;
                float4 t[8];
                float m = -1e30f;
#pragma unroll
                for (int q = 0; q < 8; q++) {
                    float4 a = kr[lane + 32 * q], b = b4[lane + 32 * q];
                    t[q].x = a.x + b.x; t[q].y = a.y + b.y;
                    t[q].z = a.z + b.z; t[q].w = a.w + b.w;
                    m = fmaxf(m, fmaxf(fmaxf(t[q].x, t[q].y), fmaxf(t[q].z, t[q].w)));
                }
#pragma unroll
                for (int o = 16; o; o >>= 1) m = fmaxf(m, __shfl_xor_sync(0xffffffffu, m, o));
                float s = 0.f;
#pragma unroll
                for (int q = 0; q < 8; q++)
                    s += ex2f(t[q].x - m) + ex2f(t[q].y - m) + ex2f(t[q].z - m) + ex2f(t[q].w - m);
#pragma unroll
                for (int o = 16; o; o >>= 1) s += __shfl_xor_sync(0xffffffffu, s, o);
                if (lane == 0) {
                    float an = S->lmu2s[r] - (m + lg2f(s));
                    atomicAdd(&S->errAcc, fabsf(an - S->A2s[r]));
                    S->A2s[r] = an;
                }
            }
            __syncthreads();
            if (tid == 0) atomicAdd(&g_err[iter], S->errAcc);

            float ar[32];
#pragma unroll
            for (int r = 0; r < 32; r++) ar[r] = S->A2s[r];
            float m0=-1e30f, m1=-1e30f, m2=-1e30f, m3=-1e30f;
#pragma unroll
            for (int r = 0; r < 32; r++) {
                const float* kr = S->K2 + r * RS + tid;
                float a = ar[r];
                m0 = fmaxf(m0, kr[0]   + a);
                m1 = fmaxf(m1, kr[256] + a);
                m2 = fmaxf(m2, kr[512] + a);
                m3 = fmaxf(m3, kr[768] + a);
            }
            float s0=0.f, s1=0.f, s2=0.f, s3=0.f;
#pragma unroll
            for (int r = 0; r < 32; r++) {
                const float* kr = S->K2 + r * RS + tid;
                float a = ar[r];
                s0 += ex2f(kr[0]   + a - m0);
                s1 += ex2f(kr[256] + a - m1);
                s2 += ex2f(kr[512] + a - m2);
                s3 += ex2f(kr[768] + a - m3);
            }
            float2* cp = g_cp + bid * PP;
            cp[tid]       = make_float2(m0, s0);
            cp[tid + 256] = make_float2(m1, s1);
            cp[tid + 512] = make_float2(m2, s2);
            cp[tid + 768] = make_float2(m3, s3);
        }
        gbar(g0 + (++bk));

        // phase 2: combine column partials -> B
        if (tid < 32) {
            const int gcol = sub * 32 + tid;
            float M = -1e30f, Ss = 0.f;
#pragma unroll
            for (int c = 0; c < 32; c++) {
                float2 p = __ldcg(&g_cp[(nb * 32 + c) * PP + gcol]);
                float Mn = fmaxf(M, p.x);
                Ss = Ss * ex2f(M - Mn) + p.y * ex2f(p.x - Mn);
                M = Mn;
            }
            g_b2[nb * PP + gcol] = S->lnu2s[tid] - (M + lg2f(Ss));
        }
        gbar(g0 + (++bk));
    }

    // ---- final cost: cost_n = -eps*ln2 * sum 2^(K2+A+B) * K2 ----
    {
        const float4* gb4 = (const float4*)(g_b2 + nb * PP);
        ((float4*)S->bb)[tid] = __ldcg(gb4 + tid);
        __syncthreads();
        float ar[32];
#pragma unroll
        for (int r = 0; r < 32; r++) ar[r] = S->A2s[r];
        const float bc0 = S->bb[tid],       bc1 = S->bb[tid + 256];
        const float bc2 = S->bb[tid + 512], bc3 = S->bb[tid + 768];
        float acc = 0.f;
#pragma unroll 8
        for (int r = 0; r < 32; r++) {
            const float* kr = S->K2 + r * RS + tid;
            float a = ar[r];
            float k0 = kr[0], k1 = kr[256], k2 = kr[512], k3 = kr[768];
            acc = fmaf(ex2f(k0 + a + bc0), k0, acc);
            acc = fmaf(ex2f(k1 + a + bc1), k1, acc);
            acc = fmaf(ex2f(k2 + a + bc2), k2, acc);
            acc = fmaf(ex2f(k3 + a + bc3), k3, acc);
        }
        S->redd[tid] = (double)acc; __syncthreads();
        for (int s = TPB/2; s > 0; s >>= 1) { if (tid < s) S->redd[tid] += S->redd[tid+s]; __syncthreads(); }
        if (tid == 0) atomicAdd(&g_cost[nb], S->redd[0]);
    }
    gbar(g0 + (++bk));
    if (sub == 0 && tid == 0) {
        double cv = __ldcg(&g_cost[nb]);
        gout[nb] = (float)(-(double)EPSV * (double)LN2F * cv);
    }
}

extern "C" void kernel_launch(void* const* d_in, const int* in_sizes, int n_in,
                              void* d_out, int out_size) {
    const float* x  = (const float*)d_in[0];
    const float* y  = (const float*)d_in[1];
    const float* xw = (const float*)d_in[2];
    const float* yw = (const float*)d_in[3];
    float* out = (float*)d_out;
    size_t smem = sizeof(Smem);
    cudaFuncSetAttribute(sinkhorn_kernel, cudaFuncAttributeMaxDynamicSharedMemorySize, (int)smem);
    sinkhorn_kernel<<<NCTA, TPB, smem>>>(x, y, xw, yw, out);
}